// round 2
// baseline (speedup 1.0000x reference)
#include <cuda_runtime.h>
#include <cstddef>

#define NROWS 16384
#define INDIM 768
#define CDIM  256
#define KCODES 4096

// ---- device scratch (static: allowed; no runtime allocation) ----
__device__ float g_zqsum[NROWS * CDIM];      // running zq sum -> decoder input
__device__ float g_esq[4][KCODES];           // ||E_k||^2 per codebook (ref rounding)
__device__ float g_ze2[NROWS];               // ||ze||^2 for current stage
__device__ int   g_nn[4][NROWS];             // argmin indices per stage

// ============================================================================
// Generic fp32 SGEMM with bias:  C[M,Nn] = A[M,Kd] @ B[Kd,Nn] + bias[Nn]
// Accumulation: single accumulator per output element, ascending k, fused fma
// (matches Eigen gebp's chain). 128x128 tile, 8x8 per thread.
// ============================================================================
__global__ __launch_bounds__(256) void sgemm_bias_kernel(
    const float* __restrict__ A, const float* __restrict__ B,
    const float* __restrict__ bias, float* __restrict__ C,
    int M, int Kd, int Nn)
{
    __shared__ __align__(16) float As[32][132];  // [kk][mm]
    __shared__ __align__(16) float Bs[32][132];  // [kk][nn]

    const int tid = threadIdx.x;
    const int tx = tid & 15;
    const int ty = tid >> 4;
    const int m0 = blockIdx.y * 128;
    const int n0 = blockIdx.x * 128;

    float acc[8][8];
#pragma unroll
    for (int i = 0; i < 8; i++)
#pragma unroll
        for (int j = 0; j < 8; j++) acc[i][j] = 0.f;

    for (int k0 = 0; k0 < Kd; k0 += 32) {
#pragma unroll
        for (int i = 0; i < 16; i++) {
            int idx = tid + i * 256;
            int mm = idx >> 5, kk = idx & 31;
            As[kk][mm] = A[(size_t)(m0 + mm) * Kd + (k0 + kk)];
        }
#pragma unroll
        for (int i = 0; i < 16; i++) {
            int idx = tid + i * 256;
            int kk = idx >> 7, nn = idx & 127;
            Bs[kk][nn] = B[(size_t)(k0 + kk) * Nn + (n0 + nn)];
        }
        __syncthreads();

#pragma unroll
        for (int kk = 0; kk < 32; kk++) {
            float4 a0 = *(const float4*)&As[kk][ty * 4];
            float4 a1 = *(const float4*)&As[kk][64 + ty * 4];
            float4 b0 = *(const float4*)&Bs[kk][tx * 4];
            float4 b1 = *(const float4*)&Bs[kk][64 + tx * 4];
            float a[8] = {a0.x, a0.y, a0.z, a0.w, a1.x, a1.y, a1.z, a1.w};
            float b[8] = {b0.x, b0.y, b0.z, b0.w, b1.x, b1.y, b1.z, b1.w};
#pragma unroll
            for (int i = 0; i < 8; i++)
#pragma unroll
                for (int j = 0; j < 8; j++)
                    acc[i][j] = fmaf(a[i], b[j], acc[i][j]);
        }
        __syncthreads();
    }

#pragma unroll
    for (int i = 0; i < 8; i++) {
        int row = m0 + ((i < 4) ? (ty * 4 + i) : (64 + ty * 4 + (i - 4)));
#pragma unroll
        for (int jh = 0; jh < 2; jh++) {
            int col = n0 + (jh ? (64 + tx * 4) : (tx * 4));
            float4 v;
            v.x = __fadd_rn(acc[i][jh * 4 + 0], bias[col + 0]);
            v.y = __fadd_rn(acc[i][jh * 4 + 1], bias[col + 1]);
            v.z = __fadd_rn(acc[i][jh * 4 + 2], bias[col + 2]);
            v.w = __fadd_rn(acc[i][jh * 4 + 3], bias[col + 3]);
            *(float4*)&C[(size_t)row * Nn + col] = v;
        }
    }
}

// ============================================================================
// ||E_k||^2: one thread per code, SEQUENTIAL ascending c, separate mul+add
// (replicates XLA's fl(e^2) then fadd chain; no fma contraction).
// ============================================================================
__global__ void esq_kernel(const float* __restrict__ E, int stage)
{
    int row = blockIdx.x * 256 + threadIdx.x;
    if (row >= KCODES) return;
    const float* e = E + (size_t)row * CDIM;
    float s = 0.f;
#pragma unroll 8
    for (int c = 0; c < CDIM; c++) {
        float v = e[c];
        s = __fadd_rn(s, __fmul_rn(v, v));
    }
    g_esq[stage][row] = s;
}

// ============================================================================
// ||ze||^2 per row: one thread per row, sequential ascending, mul+add.
// ============================================================================
__global__ void rownorm_kernel(const float* __restrict__ ze)
{
    int row = blockIdx.x * 256 + threadIdx.x;
    if (row >= NROWS) return;
    const float* p = ze + (size_t)row * CDIM;
    float s = 0.f;
#pragma unroll 8
    for (int c = 0; c < CDIM; c++) {
        float v = __ldg(p + c);
        s = __fadd_rn(s, __fmul_rn(v, v));
    }
    g_ze2[row] = s;
}

// ============================================================================
// Fused score-GEMM + argmin over K=4096 codes, replicating the reference's
// fp32 rounding:  d_k = fl( fl( Z - fl(2*s_k) ) + esq_k ).
// Score s_k accumulated ascending-c single-chain fma (Eigen-compatible).
// Tie-break: lowest index (jnp.argmin first-occurrence).
// ============================================================================
__global__ __launch_bounds__(256) void vq_argmin_kernel(
    const float* __restrict__ ze,   // NROWS x CDIM
    const float* __restrict__ E,    // KCODES x CDIM
    int stage)
{
    __shared__ __align__(16) float As[32][132];  // ze tile [kk][mm]
    __shared__ __align__(16) float Bs[32][132];  // E^T tile [kk][code]

    const int tid = threadIdx.x;
    const int tx = tid & 15;
    const int ty = tid >> 4;
    const int m0 = blockIdx.x * 128;
    const float* __restrict__ esq = g_esq[stage];

    // per-row constant Z = ||ze||^2 (reference includes it; its rounding at
    // ulp(~384) decides near-ties, so we must replicate it exactly)
    float zrow[8];
#pragma unroll
    for (int i = 0; i < 8; i++) {
        int row = (i < 4) ? (ty * 4 + i) : (64 + ty * 4 + (i - 4));
        zrow[i] = g_ze2[m0 + row];
    }

    float bestv[8];
    int   besti[8];
#pragma unroll
    for (int i = 0; i < 8; i++) { bestv[i] = 3.4e38f; besti[i] = 0; }

    for (int cb = 0; cb < KCODES; cb += 128) {
        float acc[8][8];
#pragma unroll
        for (int i = 0; i < 8; i++)
#pragma unroll
            for (int j = 0; j < 8; j++) acc[i][j] = 0.f;

        for (int c0 = 0; c0 < CDIM; c0 += 32) {
#pragma unroll
            for (int i = 0; i < 16; i++) {
                int idx = tid + i * 256;
                int mm = idx >> 5, kk = idx & 31;
                As[kk][mm] = ze[(size_t)(m0 + mm) * CDIM + (c0 + kk)];
            }
#pragma unroll
            for (int i = 0; i < 16; i++) {
                int idx = tid + i * 256;
                int code = idx >> 5, kk = idx & 31;
                Bs[kk][code] = E[(size_t)(cb + code) * CDIM + (c0 + kk)];
            }
            __syncthreads();

#pragma unroll
            for (int kk = 0; kk < 32; kk++) {
                float4 a0 = *(const float4*)&As[kk][ty * 4];
                float4 a1 = *(const float4*)&As[kk][64 + ty * 4];
                float4 b0 = *(const float4*)&Bs[kk][tx * 4];
                float4 b1 = *(const float4*)&Bs[kk][64 + tx * 4];
                float a[8] = {a0.x, a0.y, a0.z, a0.w, a1.x, a1.y, a1.z, a1.w};
                float b[8] = {b0.x, b0.y, b0.z, b0.w, b1.x, b1.y, b1.z, b1.w};
#pragma unroll
                for (int i = 0; i < 8; i++)
#pragma unroll
                    for (int j = 0; j < 8; j++)
                        acc[i][j] = fmaf(a[i], b[j], acc[i][j]);
            }
            __syncthreads();
        }

        // d = fl( fl(Z - fl(2*s)) + esq )   -- exact replication of
        // (||ze||^2 - 2.0*(ze@E.T)) + ||E||^2 elementwise fp32 rounding
#pragma unroll
        for (int j = 0; j < 8; j++) {
            int code = cb + ((j < 4) ? (tx * 4 + j) : (64 + tx * 4 + (j - 4)));
            float eq = esq[code];
#pragma unroll
            for (int i = 0; i < 8; i++) {
                float t = __fmul_rn(2.0f, acc[i][j]);       // exact
                float a = __fadd_rn(zrow[i], -t);           // fl(Z - 2s)
                float v = __fadd_rn(a, eq);                 // fl(... + e)
                if (v < bestv[i]) { bestv[i] = v; besti[i] = code; }
            }
        }
    }

    // cross-thread reduction over the 16 tx lanes that share each row
    __syncthreads();
    float* rv = &As[0][0];           // 128*16 floats
    int*   ri = (int*)&Bs[0][0];     // 128*16 ints
#pragma unroll
    for (int i = 0; i < 8; i++) {
        int row = (i < 4) ? (ty * 4 + i) : (64 + ty * 4 + (i - 4));
        rv[row * 16 + tx] = bestv[i];
        ri[row * 16 + tx] = besti[i];
    }
    __syncthreads();
    if (tid < 128) {
        float bv = rv[tid * 16];
        int   bi = ri[tid * 16];
#pragma unroll
        for (int t = 1; t < 16; t++) {
            float v = rv[tid * 16 + t];
            int  ix = ri[tid * 16 + t];
            if (v < bv || (v == bv && ix < bi)) { bv = v; bi = ix; }
        }
        g_nn[stage][m0 + tid] = bi;
    }
}

// ============================================================================
// Gather: zq = E[nn]; residual ze_next = fl(ze - zq); nn as float; accumulate
// zq_sum left-associated. Stage 3 additionally forms the straight-through
// decoder input  fl( ze1 + fl(zq_sum - ze1) )  in place of g_zqsum.
// ============================================================================
__global__ void gather_kernel(const float* __restrict__ ze,
                              const float* __restrict__ E,
                              float* __restrict__ zq_out,
                              float* __restrict__ ze_next,   // null on stage 3
                              float* __restrict__ nn_f,
                              const float* __restrict__ ze1, // stage 3 only
                              int stage)
{
    int row = blockIdx.x;
    int c = threadIdx.x;
    int idx = g_nn[stage][row];
    float q = E[(size_t)idx * CDIM + c];
    size_t o = (size_t)row * CDIM + c;
    zq_out[o] = q;
    if (ze_next) ze_next[o] = __fadd_rn(ze[o], -q);
    float s = (stage == 0) ? q : __fadd_rn(g_zqsum[o], q);
    if (stage == 3) {
        float z1 = ze1[o];
        s = __fadd_rn(z1, __fadd_rn(s, -z1));   // ze1 + (zq_sum - ze1)
    }
    g_zqsum[o] = s;
    if (c == 0) nn_f[row] = (float)idx;
}

// ============================================================================
// kernel_launch
// Output layout (float32, reference return order, flattened):
//   x_hat [N,768] | ze_1..ze_4 [N,256] | zq_1..zq_4 [N,256] | nn_1..nn_4 [N]
// ============================================================================
extern "C" void kernel_launch(void* const* d_in, const int* in_sizes, int n_in,
                              void* d_out, int out_size)
{
    const float* x     = (const float*)d_in[0];
    const float* W_enc = (const float*)d_in[1];
    const float* b_enc = (const float*)d_in[2];
    const float* E[4]  = {(const float*)d_in[3], (const float*)d_in[4],
                          (const float*)d_in[5], (const float*)d_in[6]};
    const float* W_dec = (const float*)d_in[7];
    const float* b_dec = (const float*)d_in[8];

    float* out = (float*)d_out;

    const size_t NC      = (size_t)NROWS * CDIM;
    const size_t OFF_ZE  = (size_t)NROWS * INDIM;
    const size_t OFF_ZQ  = OFF_ZE + 4 * NC;
    const size_t OFF_NN  = OFF_ZQ + 4 * NC;

    float* xhat = out;
    const float* ze1 = out + OFF_ZE;

    void* zqsum_ptr = nullptr;
    cudaGetSymbolAddress(&zqsum_ptr, g_zqsum);

    // codebook norms (independent, front-load)
    for (int s = 0; s < 4; s++)
        esq_kernel<<<(KCODES + 255) / 256, 256>>>(E[s], s);

    // encoder: ze_1 = x @ W_enc + b_enc
    sgemm_bias_kernel<<<dim3(CDIM / 128, NROWS / 128), 256>>>(
        x, W_enc, b_enc, out + OFF_ZE, NROWS, INDIM, CDIM);

    // 4 sequential VQ stages
    for (int s = 0; s < 4; s++) {
        const float* zes = out + OFF_ZE + (size_t)s * NC;
        rownorm_kernel<<<NROWS / 256, 256>>>(zes);
        vq_argmin_kernel<<<NROWS / 128, 256>>>(zes, E[s], s);
        float* zenext = (s < 3) ? (out + OFF_ZE + (size_t)(s + 1) * NC) : nullptr;
        gather_kernel<<<NROWS, 256>>>(zes, E[s],
                                      out + OFF_ZQ + (size_t)s * NC,
                                      zenext,
                                      out + OFF_NN + (size_t)s * NROWS,
                                      ze1, s);
    }

    // decoder: x_hat = decoder_input @ W_dec + b_dec
    sgemm_bias_kernel<<<dim3(INDIM / 128, NROWS / 128), 256>>>(
        (const float*)zqsum_ptr, W_dec, b_dec, xhat, NROWS, CDIM, INDIM);
}